// round 10
// baseline (speedup 1.0000x reference)
#include <cuda_runtime.h>
#include <math.h>

#define BATCH 8
#define NVERT 8192
#define NPD 64
#define NSAMP (NPD*NPD)      // 4096
#define CH 128               // chunks per batch
#define JCHUNK (NVERT/CH)    // 64 j per block
#define KP 32                // kpairs per block
#define NSTEP 4              // k16 MMA steps
#define STR 68               // u64 row stride (STR%16==4 -> conflict-free frag gather)

// ---- device scratch ----
__device__ float4 g_stats[BATCH*4];
__device__ float  g_coeff[BATCH];
__device__ float  g_partial[BATCH*CH*NSAMP];   // 16.8 MB
__device__ float  g_K[BATCH*NSAMP];
__device__ float  g_ssum[BATCH*32];

__device__ __forceinline__ float ex2f(float x) {
    float y; asm("ex2.approx.ftz.f32 %0, %1;" : "=f"(y) : "f"(x)); return y;
}
// pack (ve -> low bf16, vo -> high bf16) + residual pack
__device__ __forceinline__ void split_pair(float ve, float vo, unsigned& hi, unsigned& lo) {
    asm("cvt.rn.bf16x2.f32 %0, %1, %2;" : "=r"(hi) : "f"(vo), "f"(ve));
    float he = __uint_as_float(hi << 16);
    float ho = __uint_as_float(hi & 0xFFFF0000u);
    float le = ve - he, l_o = vo - ho;
    asm("cvt.rn.bf16x2.f32 %0, %1, %2;" : "=r"(lo) : "f"(l_o), "f"(le));
}
__device__ __forceinline__ void mma_bf16(float* d, const unsigned* a, unsigned b0, unsigned b1) {
    asm("mma.sync.aligned.m16n8k16.row.col.f32.bf16.bf16.f32 "
        "{%0,%1,%2,%3}, {%4,%5,%6,%7}, {%8,%9}, {%0,%1,%2,%3};"
        : "+f"(d[0]), "+f"(d[1]), "+f"(d[2]), "+f"(d[3])
        : "r"(a[0]), "r"(a[1]), "r"(a[2]), "r"(a[3]), "r"(b0), "r"(b1));
}

// ============ Kernel 1: partial stats (32 blocks, 512 thr) ============
__global__ void __launch_bounds__(512) k_stats(const float* __restrict__ T) {
    const int bb = blockIdx.x >> 2, part = blockIdx.x & 3;
    const int tid = threadIdx.x;
    const float4* t4 = (const float4*)(T + (size_t)bb * NVERT * 2) + part * 1024;
    float sx = 0.f, sxx = 0.f, sy = 0.f, syy = 0.f;
    #pragma unroll
    for (int k = 0; k < 2; ++k) {
        float4 v = t4[tid + k * 512];           // (x0,y0,x1,y1)
        sx  += v.x + v.z;  sy  += v.y + v.w;
        sxx += v.x*v.x + v.z*v.z;  syy += v.y*v.y + v.w*v.w;
    }
    #pragma unroll
    for (int o = 16; o; o >>= 1) {
        sx  += __shfl_xor_sync(~0u, sx,  o);
        sxx += __shfl_xor_sync(~0u, sxx, o);
        sy  += __shfl_xor_sync(~0u, sy,  o);
        syy += __shfl_xor_sync(~0u, syy, o);
    }
    __shared__ float4 sW[16];
    if ((tid & 31) == 0) sW[tid >> 5] = make_float4(sx, sxx, sy, syy);
    __syncthreads();
    if (tid == 0) {
        float4 r = sW[0];
        #pragma unroll
        for (int w = 1; w < 16; ++w) {
            r.x += sW[w].x; r.y += sW[w].y; r.z += sW[w].z; r.w += sW[w].w;
        }
        g_stats[blockIdx.x] = r;
    }
}

// ============ Kernel 2: fill (exp->bf16 split) + barrier-free MMA GEMM ============
// grid = 1024 (bb = blk>>7, ch = blk&127), 128 threads (4 warps).
__global__ void __launch_bounds__(128) k_gemm(const float* __restrict__ T,
                                              const float* __restrict__ S)
{
    // u64 word at [gi(kp)][c] = (bf16x2 word for kpair q | word for kpair q+4)
    // gi(kp) = (kp>>3)*4 + (kp&3), half = (kp>>2)&1
    __shared__ __align__(16) unsigned long long sAh[16*STR], sAl[16*STR];
    __shared__ __align__(16) unsigned long long sBh[16*STR], sBl[16*STR];
    __shared__ __align__(16) float2 sT[JCHUNK];
    __shared__ float sG[NPD];
    __shared__ float sKx;

    const int tid  = threadIdx.x;
    const int wid  = tid >> 5;
    const int lane = tid & 31;
    const int bb   = blockIdx.x >> 7;
    const int ch   = blockIdx.x & 127;

    if (tid < 32)
        ((float4*)sT)[tid] = ((const float4*)(T + (size_t)(bb * NVERT + ch * JCHUNK) * 2))[tid];
    if (tid >= 64) sG[tid - 64] = S[(tid - 64) * 2 + 1];   // S[0,c,1] = g[c]
    if (tid == 32) {
        double Sx = 0, Sxx = 0, Sy = 0, Syy = 0;
        #pragma unroll
        for (int i = 0; i < 4; ++i) {
            float4 r = __ldcg(&g_stats[bb * 4 + i]);
            Sx += r.x; Sxx += r.y; Sy += r.z; Syy += r.w;
        }
        const double n = (double)NVERT;
        double vx = (Sxx - Sx * Sx / n) / (n - 1.0);
        double vy = (Syy - Sy * Sy / n) / (n - 1.0);
        if (vx < 0.0) vx = 0.0;
        if (vy < 0.0) vy = 0.0;
        double sigma = 0.5 * (sqrt(vx) + sqrt(vy));
        const double bd = 1.0 / 63.0;
        if (sigma < bd) sigma = bd;
        const double p  = exp2(13.0 / 3.0);      // CN=-p/2, CF=p/(2pi)
        const double s2 = sigma * sigma;
        sKx = (float)((-0.5 * p) / s2 * 1.4426950408889634);
        if (ch == 0) g_coeff[bb] = (float)((p / (2.0 * M_PI)) / s2 / (double)NVERT);
    }
    __syncthreads();
    const float kx = sKx;

    // ---- fill: 2048 (kp,c) slots x (A,B); 64 independent ex2 per thread ----
    #pragma unroll 4
    for (int i = 0; i < 16; ++i) {
        const int slot = tid + i * 128;
        const int kp = slot >> 6, c = slot & 63;
        const float2 t0 = sT[2 * kp];
        const float2 t1 = sT[2 * kp + 1];
        const float gv = sG[c];
        const int gi = ((kp >> 3) * 4 + (kp & 3)) * STR + c;
        const int hf = (kp >> 2) & 1;
        float d0 = gv - t0.x, d1 = gv - t1.x;
        float v0 = ex2f(kx * (d0 * d0)), v1 = ex2f(kx * (d1 * d1));
        unsigned hi, lo; split_pair(v0, v1, hi, lo);
        ((unsigned*)sAh)[gi * 2 + hf] = hi;
        ((unsigned*)sAl)[gi * 2 + hf] = lo;
        d0 = gv - t0.y; d1 = gv - t1.y;
        v0 = ex2f(kx * (d0 * d0)); v1 = ex2f(kx * (d1 * d1));
        split_pair(v0, v1, hi, lo);
        ((unsigned*)sBh)[gi * 2 + hf] = hi;
        ((unsigned*)sBl)[gi * 2 + hf] = lo;
    }
    __syncthreads();

    // ---- barrier-free GEMM: 4 k16-steps, 3-pass bf16 split ----
    float dacc[8][4];
    #pragma unroll
    for (int nt = 0; nt < 8; ++nt)
        #pragma unroll
        for (int i = 0; i < 4; ++i) dacc[nt][i] = 0.f;

    const int g = lane >> 2, q = lane & 3;
    const int r0 = wid * 16 + g, r1 = r0 + 8;

    #pragma unroll
    for (int s = 0; s < NSTEP; ++s) {
        const int row = (s * 4 + q) * STR;
        const unsigned long long a01h = sAh[row + r0];
        const unsigned long long a23h = sAh[row + r1];
        const unsigned long long a01l = sAl[row + r0];
        const unsigned long long a23l = sAl[row + r1];
        unsigned ah[4] = { (unsigned)a01h, (unsigned)a23h,
                           (unsigned)(a01h >> 32), (unsigned)(a23h >> 32) };
        unsigned al[4] = { (unsigned)a01l, (unsigned)a23l,
                           (unsigned)(a01l >> 32), (unsigned)(a23l >> 32) };
        #pragma unroll
        for (int nt = 0; nt < 8; ++nt) {
            const unsigned long long bh = sBh[row + nt * 8 + g];
            const unsigned long long bl = sBl[row + nt * 8 + g];
            const unsigned bh0 = (unsigned)bh, bh1 = (unsigned)(bh >> 32);
            const unsigned bl0 = (unsigned)bl, bl1 = (unsigned)(bl >> 32);
            mma_bf16(dacc[nt], ah, bh0, bh1);
            mma_bf16(dacc[nt], ah, bl0, bl1);
            mma_bf16(dacc[nt], al, bh0, bh1);
        }
    }

    // ---- epilogue: rows r0/r1, cols nt*8 + 2q ----
    float* outp = g_partial + (size_t)blockIdx.x * NSAMP;
    #pragma unroll
    for (int nt = 0; nt < 8; ++nt) {
        const int n0 = nt * 8 + 2 * q;
        *(float2*)(outp + r0 * NPD + n0) = make_float2(dacc[nt][0], dacc[nt][1]);
        *(float2*)(outp + r1 * NPD + n0) = make_float2(dacc[nt][2], dacc[nt][3]);
    }
}

// ============ Kernel 3: chunk reduce + coeff scale + segment sums ============
// grid = 256 (bb = blk>>5, pp = blk&31), 128 thr; block owns 32 float4 positions.
__global__ void __launch_bounds__(128) k_reduce() {
    __shared__ __align__(16) float4 s4[128];
    const int bb = blockIdx.x >> 5, pp = blockIdx.x & 31;
    const int tid = threadIdx.x;
    const int pos = pp * 32 + (tid & 31);
    const int cg  = tid >> 5;                   // 0..3 -> 32 chunks each
    const float4* base = (const float4*)g_partial + ((size_t)bb * CH + cg * 32) * 1024 + pos;
    float4 a0 = make_float4(0.f,0.f,0.f,0.f), a1 = a0, a2 = a0, a3 = a0;
    #pragma unroll
    for (int c = 0; c < 8; ++c) {
        float4 v0 = __ldcg(base + (size_t)(c*4    ) * 1024);
        float4 v1 = __ldcg(base + (size_t)(c*4 + 1) * 1024);
        float4 v2 = __ldcg(base + (size_t)(c*4 + 2) * 1024);
        float4 v3 = __ldcg(base + (size_t)(c*4 + 3) * 1024);
        a0.x+=v0.x; a0.y+=v0.y; a0.z+=v0.z; a0.w+=v0.w;
        a1.x+=v1.x; a1.y+=v1.y; a1.z+=v1.z; a1.w+=v1.w;
        a2.x+=v2.x; a2.y+=v2.y; a2.z+=v2.z; a2.w+=v2.w;
        a3.x+=v3.x; a3.y+=v3.y; a3.z+=v3.z; a3.w+=v3.w;
    }
    a0.x += a1.x + a2.x + a3.x;  a0.y += a1.y + a2.y + a3.y;
    a0.z += a1.z + a2.z + a3.z;  a0.w += a1.w + a2.w + a3.w;
    s4[tid] = a0;
    __syncthreads();
    if (tid < 32) {
        float4 r = s4[tid];
        #pragma unroll
        for (int k = 1; k < 4; ++k) {
            float4 v = s4[tid + k * 32];
            r.x += v.x; r.y += v.y; r.z += v.z; r.w += v.w;
        }
        const float cf = __ldcg(&g_coeff[bb]);
        r.x *= cf; r.y *= cf; r.z *= cf; r.w *= cf;
        ((float4*)g_K)[bb * 1024 + pos] = r;
        float ls = r.x + r.y + r.z + r.w;
        #pragma unroll
        for (int o = 16; o; o >>= 1) ls += __shfl_xor_sync(~0u, ls, o);
        if (tid == 0) g_ssum[blockIdx.x] = ls;
    }
}

// ============ Kernel 4: normalize ============
__global__ void __launch_bounds__(256) k_norm(float* __restrict__ out) {
    __shared__ float sInv;
    const int bb = blockIdx.x, tid = threadIdx.x;
    if (tid < 32) {
        float v = __ldcg(&g_ssum[bb * 32 + tid]);
        #pragma unroll
        for (int o = 16; o; o >>= 1) v += __shfl_xor_sync(~0u, v, o);
        if (tid == 0) sInv = 1.0f / fmaxf(v, 1e-5f);
    }
    __syncthreads();
    const float inv = sInv;
    const float4* kp = (const float4*)g_K + bb * 1024;
    float4* op = (float4*)out + bb * 1024;
    #pragma unroll
    for (int k = 0; k < 4; ++k) {
        float4 v = __ldcg(kp + tid + k * 256);
        v.x *= inv; v.y *= inv; v.z *= inv; v.w *= inv;
        op[tid + k * 256] = v;
    }
}

extern "C" void kernel_launch(void* const* d_in, const int* in_sizes, int n_in,
                              void* d_out, int out_size)
{
    const float* T = (const float*)d_in[0];
    const float* S = (const float*)d_in[1];
    if (n_in >= 2 && in_sizes[0] == BATCH * NSAMP * 2 &&
        in_sizes[1] == BATCH * NVERT * 2) {
        T = (const float*)d_in[1];
        S = (const float*)d_in[0];
    }
    k_stats <<<BATCH * 4, 512>>>(T);
    k_gemm  <<<BATCH * CH, 128>>>(T, S);
    k_reduce<<<BATCH * 32, 128>>>();
    k_norm  <<<BATCH, 256>>>((float*)d_out);
}

// round 11
// speedup vs baseline: 1.0923x; 1.0923x over previous
#include <cuda_runtime.h>
#include <math.h>

#define BATCH 8
#define NVERT 8192
#define NPD 64
#define NSAMP (NPD*NPD)      // 4096
#define CH 64                // chunks (blocks) per batch
#define JCHUNK (NVERT/CH)    // 128 vertices per block
#define NSTG 2               // phase-B stages (32 kpairs each)
#define NTHR 128
#define STR 68               // u64 row stride (conflict-free frag gather)

// ---- device scratch (no allocations allowed) ----
__device__ float4   g_stats[BATCH*CH];
__device__ float    g_partial[BATCH*CH*NSAMP];  // 8 MB
__device__ float    g_K[BATCH*NSAMP];
__device__ float    g_ssum[BATCH*CH];
__device__ unsigned g_cntA[BATCH];
__device__ unsigned g_cntB[BATCH];
__device__ unsigned g_cntC[BATCH];

__device__ __forceinline__ float ex2f(float x) {
    float y; asm("ex2.approx.ftz.f32 %0, %1;" : "=f"(y) : "f"(x)); return y;
}
// pack (ve -> low bf16, vo -> high bf16) + residual pack
__device__ __forceinline__ void split_pair(float ve, float vo, unsigned& hi, unsigned& lo) {
    asm("cvt.rn.bf16x2.f32 %0, %1, %2;" : "=r"(hi) : "f"(vo), "f"(ve));
    float he = __uint_as_float(hi << 16);
    float ho = __uint_as_float(hi & 0xFFFF0000u);
    float le = ve - he, l_o = vo - ho;
    asm("cvt.rn.bf16x2.f32 %0, %1, %2;" : "=r"(lo) : "f"(l_o), "f"(le));
}
__device__ __forceinline__ void mma_bf16(float* d, const unsigned* a, unsigned b0, unsigned b1) {
    asm("mma.sync.aligned.m16n8k16.row.col.f32.bf16.bf16.f32 "
        "{%0,%1,%2,%3}, {%4,%5,%6,%7}, {%8,%9}, {%0,%1,%2,%3};"
        : "+f"(d[0]), "+f"(d[1]), "+f"(d[2]), "+f"(d[3])
        : "r"(a[0]), "r"(a[1]), "r"(a[2]), "r"(a[3]), "r"(b0), "r"(b1));
}
__device__ __forceinline__ void spin_until(volatile unsigned* p, unsigned v) {
    while (*p < v) { }
}

// ==================== single fused persistent kernel ====================
// grid = 512 blocks (batch = blk>>6, chunk = blk&63), 128 threads (4 warps).
__global__ void __launch_bounds__(NTHR, 4) k_fused(const float* __restrict__ T,
                                                   const float* __restrict__ S,
                                                   float* __restrict__ out)
{
    // split planes for 32 kpairs: u64[gi][c], gi(kp)=(kp>>3)*4+(kp&3), hf=(kp>>2)&1
    __shared__ __align__(16) unsigned long long sAh[16*STR], sAl[16*STR];
    __shared__ __align__(16) unsigned long long sBh[16*STR], sBl[16*STR];   // 34 KB
    __shared__ __align__(16) float2 sT[JCHUNK];          // 1 KB
    __shared__ __align__(16) float4 s4[NTHR];            // 2 KB
    __shared__ float  sG[NPD];
    __shared__ float4 sW[4];
    __shared__ float  sKx, sCoeff, sInv;
    __shared__ int    sIsLast;

    const int tid  = threadIdx.x;
    const int wid  = tid >> 5;
    const int lane = tid & 31;
    const int bb   = blockIdx.x >> 6;
    const int ch   = blockIdx.x & 63;

    // ---- stage T chunk + grid ----
    ((float2*)sT)[tid] = ((const float2*)(T + (size_t)(bb * NVERT + ch * JCHUNK) * 2))[tid];
    if (tid < NPD) sG[tid] = S[tid * 2 + 1];   // S[0,c,1] = g[c] exactly
    __syncthreads();

    // ================= Phase A: chunk stats + sigma =================
    {
        float2 v0 = sT[tid];                   // one vertex per thread
        float sx = v0.x, sy = v0.y;
        float sxx = v0.x * v0.x, syy = v0.y * v0.y;
        #pragma unroll
        for (int o = 16; o; o >>= 1) {
            sx  += __shfl_xor_sync(~0u, sx,  o);
            sxx += __shfl_xor_sync(~0u, sxx, o);
            sy  += __shfl_xor_sync(~0u, sy,  o);
            syy += __shfl_xor_sync(~0u, syy, o);
        }
        if (lane == 0) sW[wid] = make_float4(sx, sxx, sy, syy);
        __syncthreads();
        if (tid == 0) {
            float4 r = sW[0];
            #pragma unroll
            for (int w = 1; w < 4; ++w) {
                r.x += sW[w].x; r.y += sW[w].y; r.z += sW[w].z; r.w += sW[w].w;
            }
            g_stats[blockIdx.x] = r;
            __threadfence();
            atomicAdd(&g_cntA[bb], 1u);
            spin_until(&g_cntA[bb], CH);
            __threadfence();
        }
        __syncthreads();
    }
    if (tid < 32) {
        float4 sa = __ldcg(&g_stats[bb * CH + tid]);
        float4 sb = __ldcg(&g_stats[bb * CH + 32 + tid]);
        float sx = sa.x + sb.x, sxx = sa.y + sb.y;
        float sy = sa.z + sb.z, syy = sa.w + sb.w;
        #pragma unroll
        for (int o = 16; o; o >>= 1) {
            sx  += __shfl_xor_sync(~0u, sx,  o);
            sxx += __shfl_xor_sync(~0u, sxx, o);
            sy  += __shfl_xor_sync(~0u, sy,  o);
            syy += __shfl_xor_sync(~0u, syy, o);
        }
        if (tid == 0) {
            const double n = (double)NVERT;
            double vx = ((double)sxx - (double)sx*(double)sx/n) / (n - 1.0);
            double vy = ((double)syy - (double)sy*(double)sy/n) / (n - 1.0);
            if (vx < 0.0) vx = 0.0;
            if (vy < 0.0) vy = 0.0;
            double sigma = 0.5 * (sqrt(vx) + sqrt(vy));
            const double bd = 1.0 / 63.0;
            if (sigma < bd) sigma = bd;
            const double p  = exp2(13.0 / 3.0);   // CN=-p/2, CF=p/(2pi)
            const double s2 = sigma * sigma;
            sKx    = (float)((-0.5 * p) / s2 * 1.4426950408889634);
            sCoeff = (float)((p / (2.0 * M_PI)) / s2 / (double)NVERT);
        }
    }
    __syncthreads();
    const float kx = sKx;

    // ================= Phase B: staged fill + barrier-free MMA GEMM =================
    float dacc[8][4];
    #pragma unroll
    for (int nt = 0; nt < 8; ++nt)
        #pragma unroll
        for (int i = 0; i < 4; ++i) dacc[nt][i] = 0.f;

    const int g = lane >> 2, q = lane & 3;
    const int r0 = wid * 16 + g, r1 = r0 + 8;

    for (int st = 0; st < NSTG; ++st) {
        // ---- fill: 32 kpairs x 64 cols x (A,B); 64 independent ex2 per thread ----
        const int jb = st * 64;
        #pragma unroll 4
        for (int i = 0; i < 16; ++i) {
            const int slot = tid + i * 128;
            const int kp = slot >> 6, c = slot & 63;
            const float2 t0 = sT[jb + 2 * kp];
            const float2 t1 = sT[jb + 2 * kp + 1];
            const float gv = sG[c];
            const int gi = ((kp >> 3) * 4 + (kp & 3)) * STR + c;
            const int hf = (kp >> 2) & 1;
            float d0 = gv - t0.x, d1 = gv - t1.x;
            float v0 = ex2f(kx * (d0 * d0)), v1 = ex2f(kx * (d1 * d1));
            unsigned hi, lo; split_pair(v0, v1, hi, lo);
            ((unsigned*)sAh)[gi * 2 + hf] = hi;
            ((unsigned*)sAl)[gi * 2 + hf] = lo;
            d0 = gv - t0.y; d1 = gv - t1.y;
            v0 = ex2f(kx * (d0 * d0)); v1 = ex2f(kx * (d1 * d1));
            split_pair(v0, v1, hi, lo);
            ((unsigned*)sBh)[gi * 2 + hf] = hi;
            ((unsigned*)sBl)[gi * 2 + hf] = lo;
        }
        __syncthreads();
        // ---- barrier-free GEMM: 4 k16-steps, 3-pass bf16 split ----
        #pragma unroll
        for (int s = 0; s < 4; ++s) {
            const int row = (s * 4 + q) * STR;
            const unsigned long long a01h = sAh[row + r0];
            const unsigned long long a23h = sAh[row + r1];
            const unsigned long long a01l = sAl[row + r0];
            const unsigned long long a23l = sAl[row + r1];
            unsigned ah[4] = { (unsigned)a01h, (unsigned)a23h,
                               (unsigned)(a01h >> 32), (unsigned)(a23h >> 32) };
            unsigned al[4] = { (unsigned)a01l, (unsigned)a23l,
                               (unsigned)(a01l >> 32), (unsigned)(a23l >> 32) };
            #pragma unroll
            for (int nt = 0; nt < 8; ++nt) {
                const unsigned long long bh = sBh[row + nt * 8 + g];
                const unsigned long long bl = sBl[row + nt * 8 + g];
                const unsigned bh0 = (unsigned)bh, bh1 = (unsigned)(bh >> 32);
                const unsigned bl0 = (unsigned)bl, bl1 = (unsigned)(bl >> 32);
                mma_bf16(dacc[nt], ah, bh0, bh1);
                mma_bf16(dacc[nt], ah, bl0, bl1);
                mma_bf16(dacc[nt], al, bh0, bh1);
            }
        }
        __syncthreads();   // smem reuse safety before next stage's fill
    }

    // write this block's 64x64 partial (rows r0/r1, cols nt*8 + 2q)
    {
        float* outp = g_partial + (size_t)blockIdx.x * NSAMP;
        #pragma unroll
        for (int nt = 0; nt < 8; ++nt) {
            const int n0 = nt * 8 + 2 * q;
            *(float2*)(outp + r0 * NPD + n0) = make_float2(dacc[nt][0], dacc[nt][1]);
            *(float2*)(outp + r1 * NPD + n0) = make_float2(dacc[nt][2], dacc[nt][3]);
        }
    }
    __threadfence();
    __syncthreads();
    if (tid == 0) {
        atomicAdd(&g_cntB[bb], 1u);
        spin_until(&g_cntB[bb], CH);
        __threadfence();
    }
    __syncthreads();

    // ================= Phase C: cooperative reduce + segment sums =================
    // Block (bb,ch) reduces image float4 positions [ch*16, ch*16+16) over 64 chunks.
    {
        const int p4 = ch * 16 + (tid & 15);
        const int qq = tid >> 4;                       // 0..7
        const float4* base = (const float4*)g_partial + (size_t)bb * CH * 1024 + p4;
        float4 s = make_float4(0.f, 0.f, 0.f, 0.f);
        #pragma unroll
        for (int c = 0; c < 8; ++c) {
            float4 v = __ldcg(base + (size_t)(qq * 8 + c) * 1024);
            s.x += v.x; s.y += v.y; s.z += v.z; s.w += v.w;
        }
        s4[tid] = s;
        __syncthreads();
        if (tid < 16) {
            float4 r = s4[tid];
            #pragma unroll
            for (int k = 1; k < 8; ++k) {
                float4 v = s4[tid + k * 16];
                r.x += v.x; r.y += v.y; r.z += v.z; r.w += v.w;
            }
            const float cf = sCoeff;
            r.x *= cf; r.y *= cf; r.z *= cf; r.w *= cf;
            ((float4*)g_K)[bb * 1024 + ch * 16 + tid] = r;
            float ls = r.x + r.y + r.z + r.w;
            #pragma unroll
            for (int o = 8; o; o >>= 1) ls += __shfl_xor_sync(0xFFFFu, ls, o);
            if (tid == 0) g_ssum[bb * CH + ch] = ls;
        }
        __syncthreads();
    }
    if (tid == 0) {
        __threadfence();
        unsigned old = atomicAdd(&g_cntC[bb], 1u);
        sIsLast = (old == CH - 1) ? 1 : 0;
    }
    __syncthreads();
    if (!sIsLast) return;

    // ================= Finalize (one block per batch) =================
    __threadfence();
    if (tid < 32) {
        float v = __ldcg(&g_ssum[bb * CH + tid]) + __ldcg(&g_ssum[bb * CH + 32 + tid]);
        #pragma unroll
        for (int o = 16; o; o >>= 1) v += __shfl_xor_sync(~0u, v, o);
        if (tid == 0) sInv = 1.0f / fmaxf(v, 1e-5f);
    }
    __syncthreads();
    const float inv = sInv;
    const float4* kp = (const float4*)g_K + bb * 1024;
    float4* op = (float4*)out + bb * 1024;
    #pragma unroll
    for (int k = 0; k < 8; ++k) {
        float4 v = __ldcg(kp + tid + k * NTHR);
        v.x *= inv; v.y *= inv; v.z *= inv; v.w *= inv;
        op[tid + k * NTHR] = v;
    }
    if (tid == 0) { g_cntA[bb] = 0u; g_cntB[bb] = 0u; g_cntC[bb] = 0u; }
}

extern "C" void kernel_launch(void* const* d_in, const int* in_sizes, int n_in,
                              void* d_out, int out_size)
{
    const float* T = (const float*)d_in[0];
    const float* S = (const float*)d_in[1];
    if (n_in >= 2 && in_sizes[0] == BATCH * NSAMP * 2 &&
        in_sizes[1] == BATCH * NVERT * 2) {
        T = (const float*)d_in[1];
        S = (const float*)d_in[0];
    }
    k_fused<<<BATCH * CH, NTHR>>>(T, S, (float*)d_out);
}